// round 1
// baseline (speedup 1.0000x reference)
#include <cuda_runtime.h>
#include <cuda_bf16.h>

#define N_NODES 50000
#define N_EDGES 600000
#define F 128

// ---------------- scratch (static device globals; no runtime allocation) ----
__device__ float g_mean[N_NODES * F];
__device__ float g_h1[N_NODES * F];
__device__ float g_h2[N_NODES * F];
__device__ int   g_rowptr[N_NODES + 1];
__device__ int   g_cursor[N_NODES];
__device__ float g_invdeg[N_NODES];
__device__ int   g_csrsrc[N_EDGES];

// ---------------- CSR build -------------------------------------------------
__global__ void zero_counts_kernel() {
    int i = blockIdx.x * blockDim.x + threadIdx.x;
    if (i < N_NODES) g_cursor[i] = 0;
}

__global__ void count_kernel(const int* __restrict__ dst) {
    int e = blockIdx.x * blockDim.x + threadIdx.x;
    if (e < N_EDGES) atomicAdd(&g_cursor[dst[e]], 1);
}

// Single-block exclusive scan of 50000 counts -> rowptr, invdeg, cursor(start)
__global__ void scan_kernel() {
    const int t = threadIdx.x;
    const int SEG = (N_NODES + 1023) / 1024;  // 49
    int beg = t * SEG;
    int end = beg + SEG; if (end > N_NODES) end = N_NODES;

    int sum = 0;
    for (int i = beg; i < end; i++) sum += g_cursor[i];

    __shared__ int sA[1024], sB[1024];
    int* in = sA; int* outp = sB;
    in[t] = sum;
    __syncthreads();
    for (int off = 1; off < 1024; off <<= 1) {
        outp[t] = in[t] + ((t >= off) ? in[t - off] : 0);
        __syncthreads();
        int* tmp = in; in = outp; outp = tmp;
    }
    // in[] = inclusive scan of per-thread sums
    int running = (t == 0) ? 0 : in[t - 1];
    if (t == 1023) g_rowptr[N_NODES] = in[1023];

    for (int i = beg; i < end; i++) {
        int c = g_cursor[i];
        g_rowptr[i] = running;
        g_cursor[i] = running;  // fill cursor
        g_invdeg[i] = 1.0f / (float)(c > 1 ? c : 1);
        running += c;
    }
}

__global__ void fill_kernel(const int* __restrict__ src, const int* __restrict__ dst) {
    int e = blockIdx.x * blockDim.x + threadIdx.x;
    if (e < N_EDGES) {
        int d = dst[e];
        int pos = atomicAdd(&g_cursor[d], 1);
        g_csrsrc[pos] = src[e];
    }
}

// ---------------- neighbor mean aggregation (warp per node, no atomics) -----
__global__ void aggregate_kernel(const float* __restrict__ x) {
    int warp = (blockIdx.x * blockDim.x + threadIdx.x) >> 5;
    int lane = threadIdx.x & 31;
    if (warp >= N_NODES) return;

    int beg = g_rowptr[warp];
    int end = g_rowptr[warp + 1];

    float4 acc = make_float4(0.f, 0.f, 0.f, 0.f);
    for (int i = beg; i < end; i++) {
        int s = __ldg(&g_csrsrc[i]);
        float4 v = *(const float4*)&x[(size_t)s * F + lane * 4];
        acc.x += v.x; acc.y += v.y; acc.z += v.z; acc.w += v.w;
    }
    float inv = g_invdeg[warp];
    float4 o = make_float4(acc.x * inv, acc.y * inv, acc.z * inv, acc.w * inv);
    *(float4*)&g_mean[(size_t)warp * F + lane * 4] = o;
}

// ---------------- fused SAGE GEMM: out = X@Ws + mean@Wn + b (opt relu) ------
// Classic 128x128 tile fp32 SGEMM, K=256 handled as two 128-K phases.
__global__ __launch_bounds__(256, 2) void gemm_sage_kernel(
    const float* __restrict__ X,
    const float* __restrict__ Ws, const float* __restrict__ Wn,
    const float* __restrict__ bias,
    float* __restrict__ out, int do_relu)
{
    __shared__ __align__(16) float As[8][128];
    __shared__ __align__(16) float Bs[8][128];

    const int bm = blockIdx.x * 128;
    const int tid = threadIdx.x;
    const int tx = tid & 15;
    const int ty = tid >> 4;

    float acc[8][8];
#pragma unroll
    for (int i = 0; i < 8; i++)
#pragma unroll
        for (int j = 0; j < 8; j++) acc[i][j] = 0.f;

    // A-load mapping: thread -> (row, k-quad)
    const int a_row = tid >> 1;
    const int a_kq  = (tid & 1) * 4;
    // B-load mapping: thread -> (k, col-quad)
    const int b_kk = tid >> 5;
    const int b_j  = (tid & 31) * 4;

    for (int phase = 0; phase < 2; ++phase) {
        const float* A = phase ? g_mean : X;
        const float* W = phase ? Wn : Ws;

        for (int k0 = 0; k0 < 128; k0 += 8) {
            // load A tile (128 rows x 8 k), transposed into As[k][m]
            int gr = bm + a_row;
            float4 v = make_float4(0.f, 0.f, 0.f, 0.f);
            if (gr < N_NODES)
                v = *(const float4*)&A[(size_t)gr * F + k0 + a_kq];
            As[a_kq + 0][a_row] = v.x;
            As[a_kq + 1][a_row] = v.y;
            As[a_kq + 2][a_row] = v.z;
            As[a_kq + 3][a_row] = v.w;
            // load B tile (8 k x 128 cols)
            *(float4*)&Bs[b_kk][b_j] = *(const float4*)&W[(size_t)(k0 + b_kk) * F + b_j];

            __syncthreads();

#pragma unroll
            for (int kk = 0; kk < 8; ++kk) {
                float a[8], b[8];
                *(float4*)(a)     = *(const float4*)&As[kk][ty * 8];
                *(float4*)(a + 4) = *(const float4*)&As[kk][ty * 8 + 4];
                *(float4*)(b)     = *(const float4*)&Bs[kk][tx * 8];
                *(float4*)(b + 4) = *(const float4*)&Bs[kk][tx * 8 + 4];
#pragma unroll
                for (int i = 0; i < 8; i++)
#pragma unroll
                    for (int j = 0; j < 8; j++)
                        acc[i][j] += a[i] * b[j];
            }
            __syncthreads();
        }
    }

    // epilogue: bias (+ relu), guarded store
#pragma unroll
    for (int i = 0; i < 8; i++) {
        int gr = bm + ty * 8 + i;
        if (gr >= N_NODES) continue;
#pragma unroll
        for (int j = 0; j < 8; j += 4) {
            int c = tx * 8 + j;
            float4 o;
            o.x = acc[i][j + 0] + bias[c + 0];
            o.y = acc[i][j + 1] + bias[c + 1];
            o.z = acc[i][j + 2] + bias[c + 2];
            o.w = acc[i][j + 3] + bias[c + 3];
            if (do_relu) {
                o.x = o.x > 0.f ? o.x : 0.f;
                o.y = o.y > 0.f ? o.y : 0.f;
                o.z = o.z > 0.f ? o.z : 0.f;
                o.w = o.w > 0.f ? o.w : 0.f;
            }
            *(float4*)&out[(size_t)gr * F + c] = o;
        }
    }
}

// ---------------- launch ----------------------------------------------------
extern "C" void kernel_launch(void* const* d_in, const int* in_sizes, int n_in,
                              void* d_out, int out_size)
{
    const float* feat = (const float*)d_in[0];
    const int*   src  = (const int*)d_in[1];
    const int*   dst  = (const int*)d_in[2];
    const float* W1s = (const float*)d_in[3];
    const float* W1n = (const float*)d_in[4];
    const float* b1  = (const float*)d_in[5];
    const float* W2s = (const float*)d_in[6];
    const float* W2n = (const float*)d_in[7];
    const float* b2  = (const float*)d_in[8];
    const float* W3s = (const float*)d_in[9];
    const float* W3n = (const float*)d_in[10];
    const float* b3  = (const float*)d_in[11];
    float* out = (float*)d_out;

    void* p;
    cudaGetSymbolAddress(&p, g_h1);  float* h1 = (float*)p;
    cudaGetSymbolAddress(&p, g_h2);  float* h2 = (float*)p;

    const int TB = 256;
    // CSR build (per call; inputs fixed across replays but work is identical)
    zero_counts_kernel<<<(N_NODES + TB - 1) / TB, TB>>>();
    count_kernel<<<(N_EDGES + TB - 1) / TB, TB>>>(dst);
    scan_kernel<<<1, 1024>>>();
    fill_kernel<<<(N_EDGES + TB - 1) / TB, TB>>>(src, dst);

    const int agg_grid  = (N_NODES + 7) / 8;         // 8 warps per block
    const int gemm_grid = (N_NODES + 127) / 128;     // 391

    // layer 1
    aggregate_kernel<<<agg_grid, TB>>>(feat);
    gemm_sage_kernel<<<gemm_grid, TB>>>(feat, W1s, W1n, b1, h1, 1);
    // layer 2
    aggregate_kernel<<<agg_grid, TB>>>(h1);
    gemm_sage_kernel<<<gemm_grid, TB>>>(h1, W2s, W2n, b2, h2, 1);
    // layer 3
    aggregate_kernel<<<agg_grid, TB>>>(h2);
    gemm_sage_kernel<<<gemm_grid, TB>>>(h2, W3s, W3n, b3, out, 0);
}

// round 4
// speedup vs baseline: 1.6645x; 1.6645x over previous
#include <cuda_runtime.h>
#include <cuda_bf16.h>
#include <cstdint>

#define N_NODES 50000
#define N_EDGES 600000
#define F 128

// ---------------- scratch (static device globals; no runtime allocation) ----
__device__ float g_mean[N_NODES * F];
__device__ float g_h1[N_NODES * F];
__device__ float g_h2[N_NODES * F];
__device__ int   g_rowptr[N_NODES + 1];
__device__ int   g_cursor[N_NODES];
__device__ float g_invdeg[N_NODES];
__device__ int   g_csrsrc[N_EDGES];

// ---------------- CSR build -------------------------------------------------
__global__ void zero_counts_kernel() {
    int i = blockIdx.x * blockDim.x + threadIdx.x;
    if (i < N_NODES) g_cursor[i] = 0;
}

__global__ void count_kernel(const int* __restrict__ dst) {
    int e = blockIdx.x * blockDim.x + threadIdx.x;
    if (e < N_EDGES) atomicAdd(&g_cursor[dst[e]], 1);
}

// Single-block exclusive scan of 50000 counts -> rowptr, invdeg, cursor(start)
__global__ void scan_kernel() {
    const int t = threadIdx.x;
    const int SEG = (N_NODES + 1023) / 1024;  // 49
    int beg = t * SEG;
    int end = beg + SEG; if (end > N_NODES) end = N_NODES;

    int sum = 0;
    for (int i = beg; i < end; i++) sum += g_cursor[i];

    __shared__ int sA[1024], sB[1024];
    int* in = sA; int* outp = sB;
    in[t] = sum;
    __syncthreads();
    for (int off = 1; off < 1024; off <<= 1) {
        outp[t] = in[t] + ((t >= off) ? in[t - off] : 0);
        __syncthreads();
        int* tmp = in; in = outp; outp = tmp;
    }
    int running = (t == 0) ? 0 : in[t - 1];
    if (t == 1023) g_rowptr[N_NODES] = in[1023];

    for (int i = beg; i < end; i++) {
        int c = g_cursor[i];
        g_rowptr[i] = running;
        g_cursor[i] = running;
        g_invdeg[i] = 1.0f / (float)(c > 1 ? c : 1);
        running += c;
    }
}

__global__ void fill_kernel(const int* __restrict__ src, const int* __restrict__ dst) {
    int e = blockIdx.x * blockDim.x + threadIdx.x;
    if (e < N_EDGES) {
        int d = dst[e];
        int pos = atomicAdd(&g_cursor[d], 1);
        g_csrsrc[pos] = src[e];
    }
}

// ---------------- neighbor mean aggregation (warp per node, no atomics) -----
__global__ void aggregate_kernel(const float* __restrict__ x) {
    int warp = (blockIdx.x * blockDim.x + threadIdx.x) >> 5;
    int lane = threadIdx.x & 31;
    if (warp >= N_NODES) return;

    int beg = g_rowptr[warp];
    int end = g_rowptr[warp + 1];

    float4 acc = make_float4(0.f, 0.f, 0.f, 0.f);
    for (int i = beg; i < end; i++) {
        int s = __ldg(&g_csrsrc[i]);
        float4 v = *(const float4*)&x[(size_t)s * F + lane * 4];
        acc.x += v.x; acc.y += v.y; acc.z += v.z; acc.w += v.w;
    }
    float inv = g_invdeg[warp];
    float4 o = make_float4(acc.x * inv, acc.y * inv, acc.z * inv, acc.w * inv);
    *(float4*)&g_mean[(size_t)warp * F + lane * 4] = o;
}

// ---------------- tf32 tensor-core fused SAGE GEMM --------------------------
// out[M,128] = X @ Ws + mean @ Wn + b  (optional relu)
// Block tile 128x128, BK=32, 8 warps as 2(m) x 4(n), warp tile 64x32.
// mma.sync.aligned.m16n8k8 tf32: per warp 4 m-tiles x 4 n-tiles.

__device__ __forceinline__ uint32_t f2tf(float x) {
    uint32_t r;
    asm("cvt.rna.tf32.f32 %0, %1;" : "=r"(r) : "f"(x));
    return r;
}

__device__ __forceinline__ void mma_tf32(float* c, const uint32_t* a, const uint32_t* b) {
    asm volatile(
        "mma.sync.aligned.m16n8k8.row.col.f32.tf32.tf32.f32 "
        "{%0,%1,%2,%3}, {%4,%5,%6,%7}, {%8,%9}, {%0,%1,%2,%3};"
        : "+f"(c[0]), "+f"(c[1]), "+f"(c[2]), "+f"(c[3])
        : "r"(a[0]), "r"(a[1]), "r"(a[2]), "r"(a[3]),
          "r"(b[0]), "r"(b[1]));
}

#define PADA 36   // bank = (4*row + k) % 32 -> frag reads conflict-free
#define PADB 136  // bank = (8*k + n) % 32 -> frag reads conflict-free; STS.128 writes contiguous

__global__ __launch_bounds__(256, 2) void gemm_sage_tf32(
    const float* __restrict__ X,
    const float* __restrict__ MEAN,
    const float* __restrict__ Ws, const float* __restrict__ Wn,
    const float* __restrict__ bias,
    float* __restrict__ out, int do_relu)
{
    __shared__ uint32_t As[128 * PADA];  // 18432 B
    __shared__ uint32_t Bs[32 * PADB];   // 17408 B

    const int tid  = threadIdx.x;
    const int lane = tid & 31;
    const int wid  = tid >> 5;
    const int wm   = wid & 1;    // 2 warps along M
    const int wn   = wid >> 1;   // 4 warps along N
    const int g    = lane >> 2;  // 0..7
    const int tig  = lane & 3;   // 0..3
    const int bm   = blockIdx.x * 128;

    float c[4][4][4];
#pragma unroll
    for (int mi = 0; mi < 4; mi++)
#pragma unroll
        for (int ni = 0; ni < 4; ni++)
#pragma unroll
            for (int r = 0; r < 4; r++) c[mi][ni][r] = 0.f;

    for (int phase = 0; phase < 2; ++phase) {
        const float* A = phase ? MEAN : X;
        const float* W = phase ? Wn : Ws;

        for (int kc = 0; kc < 4; ++kc) {
            const int k0 = kc * 32;

            // ---- load A tile (128 rows x 32 k) into As[row][k], tf32-rounded
#pragma unroll
            for (int i = 0; i < 4; i++) {
                int slot = tid + 256 * i;
                int r  = slot >> 3;
                int kq = slot & 7;
                int grow = bm + r;
                float4 v = make_float4(0.f, 0.f, 0.f, 0.f);
                if (grow < N_NODES)
                    v = *(const float4*)&A[(size_t)grow * F + k0 + kq * 4];
                uint32_t* p = &As[r * PADA + kq * 4];
                p[0] = f2tf(v.x); p[1] = f2tf(v.y);
                p[2] = f2tf(v.z); p[3] = f2tf(v.w);
            }
            // ---- load W tile (32 k x 128 n) into Bs[k][n]
#pragma unroll
            for (int i = 0; i < 4; i++) {
                int slot = tid + 256 * i;
                int kr = slot >> 5;
                int nb = (slot & 31) * 4;
                float4 v = *(const float4*)&W[(size_t)(k0 + kr) * F + nb];
                uint32_t* p = &Bs[kr * PADB + nb];
                p[0] = f2tf(v.x); p[1] = f2tf(v.y);
                p[2] = f2tf(v.z); p[3] = f2tf(v.w);
            }
            __syncthreads();

#pragma unroll
            for (int ks = 0; ks < 4; ++ks) {
                uint32_t a[4][4];
                uint32_t b[4][2];
#pragma unroll
                for (int mi = 0; mi < 4; mi++) {
                    int r0 = wm * 64 + mi * 16 + g;
                    a[mi][0] = As[r0 * PADA + ks * 8 + tig];
                    a[mi][1] = As[(r0 + 8) * PADA + ks * 8 + tig];
                    a[mi][2] = As[r0 * PADA + ks * 8 + tig + 4];
                    a[mi][3] = As[(r0 + 8) * PADA + ks * 8 + tig + 4];
                }
#pragma unroll
                for (int ni = 0; ni < 4; ni++) {
                    int cb = wn * 32 + ni * 8 + g;
                    b[ni][0] = Bs[(ks * 8 + tig) * PADB + cb];
                    b[ni][1] = Bs[(ks * 8 + tig + 4) * PADB + cb];
                }
#pragma unroll
                for (int mi = 0; mi < 4; mi++)
#pragma unroll
                    for (int ni = 0; ni < 4; ni++)
                        mma_tf32(c[mi][ni], a[mi], b[ni]);
            }
            __syncthreads();
        }
    }

    // ---- epilogue: bias (+relu), float2 stores
#pragma unroll
    for (int mi = 0; mi < 4; mi++) {
        int row0 = bm + wm * 64 + mi * 16 + g;
#pragma unroll
        for (int ni = 0; ni < 4; ni++) {
            int col = wn * 32 + ni * 8 + tig * 2;
            float2 bb = *(const float2*)&bias[col];
            float2 o0, o1;
            o0.x = c[mi][ni][0] + bb.x;
            o0.y = c[mi][ni][1] + bb.y;
            o1.x = c[mi][ni][2] + bb.x;
            o1.y = c[mi][ni][3] + bb.y;
            if (do_relu) {
                o0.x = fmaxf(o0.x, 0.f); o0.y = fmaxf(o0.y, 0.f);
                o1.x = fmaxf(o1.x, 0.f); o1.y = fmaxf(o1.y, 0.f);
            }
            if (row0 < N_NODES)
                *(float2*)&out[(size_t)row0 * F + col] = o0;
            if (row0 + 8 < N_NODES)
                *(float2*)&out[(size_t)(row0 + 8) * F + col] = o1;
        }
    }
}

// ---------------- launch ----------------------------------------------------
extern "C" void kernel_launch(void* const* d_in, const int* in_sizes, int n_in,
                              void* d_out, int out_size)
{
    const float* feat = (const float*)d_in[0];
    const int*   src  = (const int*)d_in[1];
    const int*   dst  = (const int*)d_in[2];
    const float* W1s = (const float*)d_in[3];
    const float* W1n = (const float*)d_in[4];
    const float* b1  = (const float*)d_in[5];
    const float* W2s = (const float*)d_in[6];
    const float* W2n = (const float*)d_in[7];
    const float* b2  = (const float*)d_in[8];
    const float* W3s = (const float*)d_in[9];
    const float* W3n = (const float*)d_in[10];
    const float* b3  = (const float*)d_in[11];
    float* out = (float*)d_out;

    void* p;
    cudaGetSymbolAddress(&p, g_h1);   float* h1   = (float*)p;
    cudaGetSymbolAddress(&p, g_h2);   float* h2   = (float*)p;
    cudaGetSymbolAddress(&p, g_mean); float* mean = (float*)p;

    const int TB = 256;
    zero_counts_kernel<<<(N_NODES + TB - 1) / TB, TB>>>();
    count_kernel<<<(N_EDGES + TB - 1) / TB, TB>>>(dst);
    scan_kernel<<<1, 1024>>>();
    fill_kernel<<<(N_EDGES + TB - 1) / TB, TB>>>(src, dst);

    const int agg_grid  = (N_NODES + 7) / 8;      // 8 warps/block
    const int gemm_grid = (N_NODES + 127) / 128;  // 391

    // layer 1
    aggregate_kernel<<<agg_grid, TB>>>(feat);
    gemm_sage_tf32<<<gemm_grid, TB>>>(feat, mean, W1s, W1n, b1, h1, 1);
    // layer 2
    aggregate_kernel<<<agg_grid, TB>>>(h1);
    gemm_sage_tf32<<<gemm_grid, TB>>>(h1, mean, W2s, W2n, b2, h2, 1);
    // layer 3
    aggregate_kernel<<<agg_grid, TB>>>(h2);
    gemm_sage_tf32<<<gemm_grid, TB>>>(h2, mean, W3s, W3n, b3, out, 0);
}